// round 5
// baseline (speedup 1.0000x reference)
#include <cuda_runtime.h>
#include <math.h>
#include <stdint.h>

#define B_    32
#define T_    512
#define FD_   256
#define NH_   1024
#define NC_   512
#define H4_   2048
#define NOUT_ 8
#define M_    (B_ * T_)

__device__ float g_bufA[(size_t)M_ * H4_];
__device__ float g_bufB[(size_t)M_ * H4_];
__device__ float g_bufC[(size_t)M_ * NH_];
__device__ float g_bufD[(size_t)M_ * NH_];
__device__ float g_hA[2 * B_ * NC_];
__device__ float g_hB[2 * B_ * NC_];
__device__ unsigned g_bar_count;
__device__ unsigned g_bar_sense;

__device__ __forceinline__ float warpSum(float v) {
#pragma unroll
    for (int o = 16; o > 0; o >>= 1) v += __shfl_xor_sync(0xffffffffu, v, o);
    return v;
}
__device__ __forceinline__ float warpMax(float v) {
#pragma unroll
    for (int o = 16; o > 0; o >>= 1) v = fmaxf(v, __shfl_xor_sync(0xffffffffu, v, o));
    return v;
}
__device__ __forceinline__ float blockSum(float v, float* sh) {
    int lane = threadIdx.x & 31, w = threadIdx.x >> 5;
    v = warpSum(v);
    if (lane == 0) sh[w] = v;
    __syncthreads();
    if (w == 0) {
        float r = (lane < 8) ? sh[lane] : 0.f;
        r = warpSum(r);
        if (lane == 0) sh[0] = r;
    }
    __syncthreads();
    float r = sh[0];
    __syncthreads();
    return r;
}
__device__ __forceinline__ float blockMax(float v, float* sh) {
    int lane = threadIdx.x & 31, w = threadIdx.x >> 5;
    v = warpMax(v);
    if (lane == 0) sh[w] = v;
    __syncthreads();
    if (w == 0) {
        float r = (lane < 8) ? sh[lane] : -3.0e38f;
        r = warpMax(r);
        if (lane == 0) sh[0] = r;
    }
    __syncthreads();
    float r = sh[0];
    __syncthreads();
    return r;
}

// C[M,N] = A[M,K] @ W[N,K]^T + bias1 (+bias2). M,N mult of 128, K mult of 8.
__global__ __launch_bounds__(256) void sgemm_tn(
    const float* __restrict__ A, const float* __restrict__ W,
    float* __restrict__ C, const float* __restrict__ bias1,
    const float* __restrict__ bias2, int M, int N, int K)
{
    __shared__ float As[8][128];
    __shared__ float Bs[8][128];
    int tid = threadIdx.x;
    int bm = blockIdx.y * 128, bn = blockIdx.x * 128;
    int ir = tid >> 1, ic = (tid & 1) << 2;
    int tr = (tid >> 4) << 3, tc = (tid & 15) << 3;
    const float* Ap = A + (size_t)(bm + ir) * K + ic;
    const float* Wp = W + (size_t)(bn + ir) * K + ic;
    float acc[8][8];
#pragma unroll
    for (int i = 0; i < 8; i++)
#pragma unroll
        for (int j = 0; j < 8; j++) acc[i][j] = 0.f;

    for (int k0 = 0; k0 < K; k0 += 8) {
        float4 a4 = *(const float4*)(Ap + k0);
        float4 b4 = *(const float4*)(Wp + k0);
        As[ic + 0][ir] = a4.x; As[ic + 1][ir] = a4.y;
        As[ic + 2][ir] = a4.z; As[ic + 3][ir] = a4.w;
        Bs[ic + 0][ir] = b4.x; Bs[ic + 1][ir] = b4.y;
        Bs[ic + 2][ir] = b4.z; Bs[ic + 3][ir] = b4.w;
        __syncthreads();
#pragma unroll
        for (int k = 0; k < 8; ++k) {
            float ra[8], rb[8];
            *(float4*)&ra[0] = *(const float4*)&As[k][tr];
            *(float4*)&ra[4] = *(const float4*)&As[k][tr + 4];
            *(float4*)&rb[0] = *(const float4*)&Bs[k][tc];
            *(float4*)&rb[4] = *(const float4*)&Bs[k][tc + 4];
#pragma unroll
            for (int i = 0; i < 8; i++)
#pragma unroll
                for (int j = 0; j < 8; j++) acc[i][j] += ra[i] * rb[j];
        }
        __syncthreads();
    }
    float bv[8];
#pragma unroll
    for (int j = 0; j < 8; j++) {
        int col = bn + tc + j;
        float bs = bias1 ? bias1[col] : 0.f;
        if (bias2) bs += bias2[col];
        bv[j] = bs;
    }
#pragma unroll
    for (int i = 0; i < 8; i++) {
        float* cp = C + (size_t)(bm + tr + i) * N + bn + tc;
        *(float4*)cp = make_float4(acc[i][0] + bv[0], acc[i][1] + bv[1],
                                   acc[i][2] + bv[2], acc[i][3] + bv[3]);
        *(float4*)(cp + 4) = make_float4(acc[i][4] + bv[4], acc[i][5] + bv[5],
                                         acc[i][6] + bv[6], acc[i][7] + bv[7]);
    }
}

// LayerNorm + LeakyReLU (+ pad-mask zero) in place, one 256-thr block per 1024-wide row
__global__ __launch_bounds__(256) void ln_lrelu(
    float* __restrict__ X, const float* __restrict__ g,
    const float* __restrict__ be, const int* __restrict__ lens)
{
    __shared__ float sh[8];
    int row = blockIdx.x;
    float* x = X + (size_t)row * NH_;
    int tid = threadIdx.x;
    float v[4], s = 0.f, ss = 0.f;
#pragma unroll
    for (int i = 0; i < 4; i++) {
        float t = x[tid + (i << 8)];
        v[i] = t; s += t; ss += t * t;
    }
    float S = blockSum(s, sh);
    float SS = blockSum(ss, sh);
    float mean = S * (1.f / NH_);
    float inv = rsqrtf(SS * (1.f / NH_) - mean * mean + 1e-5f);
    bool z = false;
    if (lens) z = ((row & (T_ - 1)) >= lens[row >> 9]);
#pragma unroll
    for (int i = 0; i < 4; i++) {
        int c = tid + (i << 8);
        float y = (v[i] - mean) * inv * g[c] + be[c];
        y = (y >= 0.f) ? y : 0.01f * y;
        x[c] = z ? 0.f : y;
    }
}

// ---- persistent bidirectional LSTM layer: 128 co-resident CTAs, grid barrier per step ----
// dir = blockIdx.x>>6, chunk = blockIdx.x&63 -> 8 hidden cols.
// whh slice cached in smem once; cell state in registers; h ping-pongs in global.
#define WSM_FLOATS (512 * 34)
#define HS_OFF     WSM_FLOATS
#define GS_OFF     (WSM_FLOATS + 32 * 36)
#define LSTM_SMEM  ((WSM_FLOATS + 32 * 36 + 32 * 33) * 4)

__global__ __launch_bounds__(128) void lstm_layer(
    const float* __restrict__ xpf, const float* __restrict__ xpb,
    const float* __restrict__ whh,
    float* __restrict__ hA, float* __restrict__ hB,
    float* __restrict__ hcat)
{
    extern __shared__ float sm[];
    float* Wsm = sm;             // [512][34]  (k, cc)
    float* hsp = sm + HS_OFF;    // [32][36]   (k, b)
    float* gsp = sm + GS_OFF;    // [32][33]   (b, cc)
    __shared__ unsigned sh_base;

    int dir = blockIdx.x >> 6;
    int j0 = (blockIdx.x & 63) << 3;
    const float* xp = dir ? xpb : xpf;
    const float* W = whh + (size_t)dir * H4_ * NC_;
    int tid = threadIdx.x;

    // cache W slice: Wsm[k][cc] = W[col(cc)][k]
    {
        int lcc = tid >> 2;           // 0..31
        int lk4 = (tid & 3) << 2;     // 0,4,8,12
        int lcol = ((lcc >> 3) << 9) + j0 + (lcc & 7);
        const float* wp = W + (size_t)lcol * NC_;
        for (int k = lk4; k < NC_; k += 16) {
            float4 w4 = *(const float4*)(wp + k);
            float* dst = Wsm + (size_t)k * 34 + lcc;
            dst[0]      = w4.x;
            dst[34]     = w4.y;
            dst[68]     = w4.z;
            dst[102]    = w4.w;
        }
    }
    if (tid == 0) sh_base = *(volatile unsigned*)&g_bar_sense;
    __syncthreads();
    unsigned base = sh_base;

    int b0 = (tid >> 4) << 2;     // 0..28
    int cc0 = (tid & 15) << 1;    // 0..30
    int lb = tid >> 2;            // 0..31
    int lk = (tid & 3) << 3;      // 0,8,16,24

    float creg[2] = {0.f, 0.f};
    int eb0 = tid >> 3, ej0 = tid & 7;            // r=0 element
    int eb1 = (tid + 128) >> 3, ej1 = tid & 7;    // r=1 element

    for (int s = 0; s < T_; ++s) {
        int t = dir ? (T_ - 1 - s) : s;
        float acc[4][2];
#pragma unroll
        for (int j = 0; j < 2; j++) {
            int cc = cc0 + j;
            int col = ((cc >> 3) << 9) + j0 + (cc & 7);
#pragma unroll
            for (int i = 0; i < 4; i++)
                acc[i][j] = xp[((size_t)(b0 + i) * T_ + t) * H4_ + col];
        }
        if (s > 0) {
            const float* hin = ((s & 1) ? hB : hA) + dir * B_ * NC_;
            for (int k0 = 0; k0 < NC_; k0 += 32) {
                float4 h0 = *(const float4*)(hin + lb * NC_ + k0 + lk);
                float4 h1 = *(const float4*)(hin + lb * NC_ + k0 + lk + 4);
                hsp[(lk + 0) * 36 + lb] = h0.x; hsp[(lk + 1) * 36 + lb] = h0.y;
                hsp[(lk + 2) * 36 + lb] = h0.z; hsp[(lk + 3) * 36 + lb] = h0.w;
                hsp[(lk + 4) * 36 + lb] = h1.x; hsp[(lk + 5) * 36 + lb] = h1.y;
                hsp[(lk + 6) * 36 + lb] = h1.z; hsp[(lk + 7) * 36 + lb] = h1.w;
                __syncthreads();
                const float* wb = Wsm + (size_t)k0 * 34;
#pragma unroll
                for (int kk = 0; kk < 32; ++kk) {
                    float4 h4 = *(const float4*)&hsp[kk * 36 + b0];
                    float2 w2 = *(const float2*)&wb[kk * 34 + cc0];
                    acc[0][0] += h4.x * w2.x; acc[0][1] += h4.x * w2.y;
                    acc[1][0] += h4.y * w2.x; acc[1][1] += h4.y * w2.y;
                    acc[2][0] += h4.z * w2.x; acc[2][1] += h4.z * w2.y;
                    acc[3][0] += h4.w * w2.x; acc[3][1] += h4.w * w2.y;
                }
                __syncthreads();
            }
        }
#pragma unroll
        for (int j = 0; j < 2; j++)
#pragma unroll
            for (int i = 0; i < 4; i++) gsp[(b0 + i) * 33 + cc0 + j] = acc[i][j];
        __syncthreads();

        float* hout = ((s & 1) ? hA : hB) + dir * B_ * NC_;
#pragma unroll
        for (int r = 0; r < 2; r++) {
            int b = r ? eb1 : eb0;
            int jj = r ? ej1 : ej0;
            float gi = gsp[b * 33 + jj];
            float gf = gsp[b * 33 + 8 + jj];
            float gg = gsp[b * 33 + 16 + jj];
            float go = gsp[b * 33 + 24 + jj];
            float fi = 1.f / (1.f + expf(-gi));
            float ff = 1.f / (1.f + expf(-gf));
            float fo = 1.f / (1.f + expf(-go));
            float cn = ff * creg[r] + fi * tanhf(gg);
            float hv = fo * tanhf(cn);
            creg[r] = cn;
            hout[b * NC_ + j0 + jj] = hv;
            hcat[((size_t)b * T_ + t) * NH_ + dir * NC_ + j0 + jj] = hv;
        }
        __syncthreads();   // protect gsp/hsp reuse next step

        // grid-wide barrier (sense-reversing, wrap-safe)
        if (tid == 0) {
            unsigned target = base + (unsigned)s + 1u;
            __threadfence();
            unsigned old = atomicAdd(&g_bar_count, 1u);
            if (old == 127u) {
                atomicExch(&g_bar_count, 0u);
                __threadfence();
                atomicExch(&g_bar_sense, target);
            } else {
                while ((int)(*(volatile unsigned*)&g_bar_sense - target) < 0) { }
                __threadfence();
            }
        }
        __syncthreads();
    }
}

// attention pool + classifier, one CTA per batch
__global__ __launch_bounds__(256) void attn_out(
    const float* __restrict__ H, const int* __restrict__ lens,
    const float* __restrict__ w_u, const float* __restrict__ b_u,
    const float* __restrict__ Wc, const float* __restrict__ bc,
    float* __restrict__ out)
{
    __shared__ float sc[T_];
    __shared__ float pooled[NH_];
    __shared__ float red[8];
    int b = blockIdx.x;
    int tid = threadIdx.x, lane = tid & 31, w = tid >> 5;
    int len = lens[b];
    const float* Hb = H + (size_t)b * T_ * NH_;

    for (int t = w; t < T_; t += 8) {
        const float* hp = Hb + (size_t)t * NH_;
        float s = 0.f;
        for (int d = lane; d < NH_; d += 32) s += hp[d] * w_u[d];
        s = warpSum(s);
        if (lane == 0) sc[t] = s + b_u[0];
    }
    __syncthreads();

    float m = -3.0e38f;
    for (int t = tid; t < len; t += 256) m = fmaxf(m, sc[t]);
    m = blockMax(m, red);

    float ps = 0.f;
    for (int t = tid; t < T_; t += 256) {
        float e = (t < len) ? expf(sc[t] - m) : 0.f;
        sc[t] = e; ps += e;
    }
    float S = blockSum(ps, red);
    float inv = 1.f / S;

    for (int d = tid; d < NH_; d += 256) {
        float a = 0.f;
        for (int t = 0; t < len; ++t) a += sc[t] * Hb[(size_t)t * NH_ + d];
        pooled[d] = a * inv;
    }
    __syncthreads();

    {
        const float* wc = Wc + (size_t)w * NH_;
        float s = 0.f;
        for (int d = lane; d < NH_; d += 32) s += pooled[d] * wc[d];
        s = warpSum(s);
        if (lane == 0) out[b * NOUT_ + w] = s + bc[w];
    }
}

extern "C" void kernel_launch(void* const* d_in, const int* in_sizes, int n_in,
                              void* d_out, int out_size)
{
    const float* x    = (const float*)d_in[0];
    const int*   lens = (const int*)d_in[1];
    const float* W1   = (const float*)d_in[2];
    const float* b1   = (const float*)d_in[3];
    const float* g1   = (const float*)d_in[4];
    const float* be1  = (const float*)d_in[5];
    const float* W2   = (const float*)d_in[6];
    const float* b2   = (const float*)d_in[7];
    const float* g2   = (const float*)d_in[8];
    const float* be2  = (const float*)d_in[9];
    const float* wih  = (const float*)d_in[10];
    const float* whh  = (const float*)d_in[11];
    const float* bih  = (const float*)d_in[12];
    const float* bhh  = (const float*)d_in[13];
    const float* w_u  = (const float*)d_in[14];
    const float* b_u  = (const float*)d_in[15];
    const float* Wc   = (const float*)d_in[16];
    const float* bc   = (const float*)d_in[17];
    float* out = (float*)d_out;
    (void)in_sizes; (void)n_in; (void)out_size;

    float *bufA, *bufB, *bufC, *bufD, *hA, *hB;
    cudaGetSymbolAddress((void**)&bufA, g_bufA);
    cudaGetSymbolAddress((void**)&bufB, g_bufB);
    cudaGetSymbolAddress((void**)&bufC, g_bufC);
    cudaGetSymbolAddress((void**)&bufD, g_bufD);
    cudaGetSymbolAddress((void**)&hA, g_hA);
    cudaGetSymbolAddress((void**)&hB, g_hB);

    cudaFuncSetAttribute(lstm_layer, cudaFuncAttributeMaxDynamicSharedMemorySize,
                         LSTM_SMEM);

    dim3 blk(256);
    dim3 gMLP(NH_ / 128, M_ / 128);
    dim3 gXP(H4_ / 128, M_ / 128);

    sgemm_tn<<<gMLP, blk>>>(x, W1, bufD, b1, nullptr, M_, NH_, FD_);
    ln_lrelu<<<M_, blk>>>(bufD, g1, be1, nullptr);
    sgemm_tn<<<gMLP, blk>>>(bufD, W2, bufC, b2, nullptr, M_, NH_, NH_);
    ln_lrelu<<<M_, blk>>>(bufC, g2, be2, lens);

    for (int layer = 0; layer < 2; ++layer) {
        const float* inbuf = (layer == 0) ? bufC : bufD;
        float* hcat = (layer == 0) ? bufD : bufC;
        size_t wo = (size_t)layer * 2 * H4_ * NH_;
        size_t ho = (size_t)layer * 2 * H4_ * NC_;
        size_t bo = (size_t)layer * 2 * H4_;

        sgemm_tn<<<gXP, blk>>>(inbuf, wih + wo, bufA,
                               bih + bo, bhh + bo, M_, H4_, NH_);
        sgemm_tn<<<gXP, blk>>>(inbuf, wih + wo + (size_t)H4_ * NH_, bufB,
                               bih + bo + H4_, bhh + bo + H4_, M_, H4_, NH_);

        lstm_layer<<<128, 128, LSTM_SMEM>>>(bufA, bufB, whh + ho, hA, hB, hcat);
    }

    attn_out<<<B_, blk>>>(bufC, lens, w_u, b_u, Wc, bc, out);
}

// round 6
// speedup vs baseline: 1.2804x; 1.2804x over previous
#include <cuda_runtime.h>
#include <math.h>
#include <stdint.h>

#define B_    32
#define T_    512
#define FD_   256
#define NH_   1024
#define NC_   512
#define H4_   2048
#define NOUT_ 8
#define M_    (B_ * T_)

__device__ float g_bufA[(size_t)M_ * H4_];
__device__ float g_bufB[(size_t)M_ * H4_];
__device__ float g_bufC[(size_t)M_ * NH_];
__device__ float g_bufD[(size_t)M_ * NH_];
__device__ float g_hA[2 * B_ * NC_];
__device__ float g_hB[2 * B_ * NC_];
__device__ unsigned g_bar_count;
__device__ unsigned g_bar_sense;

__device__ __forceinline__ float warpSum(float v) {
#pragma unroll
    for (int o = 16; o > 0; o >>= 1) v += __shfl_xor_sync(0xffffffffu, v, o);
    return v;
}
__device__ __forceinline__ float warpMax(float v) {
#pragma unroll
    for (int o = 16; o > 0; o >>= 1) v = fmaxf(v, __shfl_xor_sync(0xffffffffu, v, o));
    return v;
}
__device__ __forceinline__ float blockSum(float v, float* sh) {
    int lane = threadIdx.x & 31, w = threadIdx.x >> 5;
    v = warpSum(v);
    if (lane == 0) sh[w] = v;
    __syncthreads();
    if (w == 0) {
        float r = (lane < 8) ? sh[lane] : 0.f;
        r = warpSum(r);
        if (lane == 0) sh[0] = r;
    }
    __syncthreads();
    float r = sh[0];
    __syncthreads();
    return r;
}
__device__ __forceinline__ float blockMax(float v, float* sh) {
    int lane = threadIdx.x & 31, w = threadIdx.x >> 5;
    v = warpMax(v);
    if (lane == 0) sh[w] = v;
    __syncthreads();
    if (w == 0) {
        float r = (lane < 8) ? sh[lane] : -3.0e38f;
        r = warpMax(r);
        if (lane == 0) sh[0] = r;
    }
    __syncthreads();
    float r = sh[0];
    __syncthreads();
    return r;
}

__device__ __forceinline__ uint32_t f2tf32(float f) {
    uint32_t r;
    asm("cvt.rna.tf32.f32 %0, %1;" : "=r"(r) : "f"(f));
    return r;
}

__device__ __forceinline__ void mma_tf32(float* c, const uint32_t* a, const uint32_t* b) {
    asm volatile(
        "mma.sync.aligned.m16n8k8.row.col.f32.tf32.tf32.f32 "
        "{%0,%1,%2,%3}, {%4,%5,%6,%7}, {%8,%9}, {%0,%1,%2,%3};"
        : "+f"(c[0]), "+f"(c[1]), "+f"(c[2]), "+f"(c[3])
        : "r"(a[0]), "r"(a[1]), "r"(a[2]), "r"(a[3]), "r"(b[0]), "r"(b[1]));
}

// ---- tf32 tensor-core GEMM: C[M,N] = A[M,K] @ W[N,K]^T + bias1 (+bias2) ----
// BM=BN=128, BK=32, 256 thr = 8 warps (2x4), warp tile 64x32.
__global__ __launch_bounds__(256) void gemm_tf32(
    const float* __restrict__ A, const float* __restrict__ W,
    float* __restrict__ C, const float* __restrict__ bias1,
    const float* __restrict__ bias2, int M, int N, int K)
{
    __shared__ uint32_t As[128][36];
    __shared__ uint32_t Bs[128][36];
    int tid = threadIdx.x;
    int lane = tid & 31, warp = tid >> 5;
    int wm = warp >> 2, wn = warp & 3;
    int lr = lane >> 2, lc = lane & 3;
    int bm = blockIdx.y * 128, bn = blockIdx.x * 128;

    float acc[4][4][4];
#pragma unroll
    for (int mt = 0; mt < 4; mt++)
#pragma unroll
        for (int nt = 0; nt < 4; nt++)
#pragma unroll
            for (int q = 0; q < 4; q++) acc[mt][nt][q] = 0.f;

    for (int k0 = 0; k0 < K; k0 += 32) {
#pragma unroll
        for (int i = 0; i < 4; i++) {
            int f = tid + (i << 8);          // 0..1023
            int row = f >> 3, c4 = (f & 7) << 2;
            float4 a4 = *(const float4*)(A + (size_t)(bm + row) * K + k0 + c4);
            float4 b4 = *(const float4*)(W + (size_t)(bn + row) * K + k0 + c4);
            uint4 ta, tb;
            ta.x = f2tf32(a4.x); ta.y = f2tf32(a4.y);
            ta.z = f2tf32(a4.z); ta.w = f2tf32(a4.w);
            tb.x = f2tf32(b4.x); tb.y = f2tf32(b4.y);
            tb.z = f2tf32(b4.z); tb.w = f2tf32(b4.w);
            *(uint4*)&As[row][c4] = ta;
            *(uint4*)&Bs[row][c4] = tb;
        }
        __syncthreads();
#pragma unroll
        for (int ks = 0; ks < 4; ks++) {
            int kc = ks << 3;
            uint32_t af[4][4], bf[4][2];
#pragma unroll
            for (int mt = 0; mt < 4; mt++) {
                int rb = wm * 64 + mt * 16;
                af[mt][0] = As[rb + lr][kc + lc];
                af[mt][1] = As[rb + lr + 8][kc + lc];
                af[mt][2] = As[rb + lr][kc + lc + 4];
                af[mt][3] = As[rb + lr + 8][kc + lc + 4];
            }
#pragma unroll
            for (int nt = 0; nt < 4; nt++) {
                int nb = wn * 32 + nt * 8;
                bf[nt][0] = Bs[nb + lr][kc + lc];
                bf[nt][1] = Bs[nb + lr][kc + lc + 4];
            }
#pragma unroll
            for (int mt = 0; mt < 4; mt++)
#pragma unroll
                for (int nt = 0; nt < 4; nt++)
                    mma_tf32(acc[mt][nt], af[mt], bf[nt]);
        }
        __syncthreads();
    }

#pragma unroll
    for (int nt = 0; nt < 4; nt++) {
        int col = bn + wn * 32 + nt * 8 + (lc << 1);
        float b0 = bias1 ? bias1[col] : 0.f;
        float b1 = bias1 ? bias1[col + 1] : 0.f;
        if (bias2) { b0 += bias2[col]; b1 += bias2[col + 1]; }
#pragma unroll
        for (int mt = 0; mt < 4; mt++) {
            int row = bm + wm * 64 + mt * 16 + lr;
            float2 v0 = make_float2(acc[mt][nt][0] + b0, acc[mt][nt][1] + b1);
            float2 v1 = make_float2(acc[mt][nt][2] + b0, acc[mt][nt][3] + b1);
            *(float2*)(C + (size_t)row * N + col) = v0;
            *(float2*)(C + (size_t)(row + 8) * N + col) = v1;
        }
    }
}

// LayerNorm + LeakyReLU (+ pad-mask zero) in place, one 256-thr block per 1024-wide row
__global__ __launch_bounds__(256) void ln_lrelu(
    float* __restrict__ X, const float* __restrict__ g,
    const float* __restrict__ be, const int* __restrict__ lens)
{
    __shared__ float sh[8];
    int row = blockIdx.x;
    float* x = X + (size_t)row * NH_;
    int tid = threadIdx.x;
    float v[4], s = 0.f, ss = 0.f;
#pragma unroll
    for (int i = 0; i < 4; i++) {
        float t = x[tid + (i << 8)];
        v[i] = t; s += t; ss += t * t;
    }
    float S = blockSum(s, sh);
    float SS = blockSum(ss, sh);
    float mean = S * (1.f / NH_);
    float inv = rsqrtf(SS * (1.f / NH_) - mean * mean + 1e-5f);
    bool z = false;
    if (lens) z = ((row & (T_ - 1)) >= lens[row >> 9]);
#pragma unroll
    for (int i = 0; i < 4; i++) {
        int c = tid + (i << 8);
        float y = (v[i] - mean) * inv * g[c] + be[c];
        y = (y >= 0.f) ? y : 0.01f * y;
        x[c] = z ? 0.f : y;
    }
}

// ---- persistent bidirectional LSTM layer: 128 co-resident CTAs, grid barrier per step ----
#define WSM_FLOATS (512 * 34)
#define HS_OFF     WSM_FLOATS
#define GS_OFF     (WSM_FLOATS + 32 * 36)
#define LSTM_SMEM  ((WSM_FLOATS + 32 * 36 + 32 * 33) * 4)

__global__ __launch_bounds__(128) void lstm_layer(
    const float* __restrict__ xpf, const float* __restrict__ xpb,
    const float* __restrict__ whh,
    float* __restrict__ hA, float* __restrict__ hB,
    float* __restrict__ hcat)
{
    extern __shared__ float sm[];
    float* Wsm = sm;             // [512][34]  (k, cc)
    float* hsp = sm + HS_OFF;    // [32][36]   (k, b)
    float* gsp = sm + GS_OFF;    // [32][33]   (b, cc)
    __shared__ unsigned sh_base;

    int dir = blockIdx.x >> 6;
    int j0 = (blockIdx.x & 63) << 3;
    const float* xp = dir ? xpb : xpf;
    const float* W = whh + (size_t)dir * H4_ * NC_;
    int tid = threadIdx.x;

    {
        int lcc = tid >> 2;
        int lk4 = (tid & 3) << 2;
        int lcol = ((lcc >> 3) << 9) + j0 + (lcc & 7);
        const float* wp = W + (size_t)lcol * NC_;
        for (int k = lk4; k < NC_; k += 16) {
            float4 w4 = *(const float4*)(wp + k);
            float* dst = Wsm + (size_t)k * 34 + lcc;
            dst[0]   = w4.x;
            dst[34]  = w4.y;
            dst[68]  = w4.z;
            dst[102] = w4.w;
        }
    }
    if (tid == 0) sh_base = *(volatile unsigned*)&g_bar_sense;
    __syncthreads();
    unsigned base = sh_base;

    int b0 = (tid >> 4) << 2;
    int cc0 = (tid & 15) << 1;
    int lb = tid >> 2;
    int lk = (tid & 3) << 3;

    float creg[2] = {0.f, 0.f};
    int eb0 = tid >> 3, ej0 = tid & 7;
    int eb1 = (tid + 128) >> 3, ej1 = tid & 7;

    for (int s = 0; s < T_; ++s) {
        int t = dir ? (T_ - 1 - s) : s;
        float acc[4][2];
#pragma unroll
        for (int j = 0; j < 2; j++) {
            int cc = cc0 + j;
            int col = ((cc >> 3) << 9) + j0 + (cc & 7);
#pragma unroll
            for (int i = 0; i < 4; i++)
                acc[i][j] = xp[((size_t)(b0 + i) * T_ + t) * H4_ + col];
        }
        if (s > 0) {
            const float* hin = ((s & 1) ? hB : hA) + dir * B_ * NC_;
            for (int k0 = 0; k0 < NC_; k0 += 32) {
                float4 h0 = *(const float4*)(hin + lb * NC_ + k0 + lk);
                float4 h1 = *(const float4*)(hin + lb * NC_ + k0 + lk + 4);
                hsp[(lk + 0) * 36 + lb] = h0.x; hsp[(lk + 1) * 36 + lb] = h0.y;
                hsp[(lk + 2) * 36 + lb] = h0.z; hsp[(lk + 3) * 36 + lb] = h0.w;
                hsp[(lk + 4) * 36 + lb] = h1.x; hsp[(lk + 5) * 36 + lb] = h1.y;
                hsp[(lk + 6) * 36 + lb] = h1.z; hsp[(lk + 7) * 36 + lb] = h1.w;
                __syncthreads();
                const float* wb = Wsm + (size_t)k0 * 34;
#pragma unroll
                for (int kk = 0; kk < 32; ++kk) {
                    float4 h4 = *(const float4*)&hsp[kk * 36 + b0];
                    float2 w2 = *(const float2*)&wb[kk * 34 + cc0];
                    acc[0][0] += h4.x * w2.x; acc[0][1] += h4.x * w2.y;
                    acc[1][0] += h4.y * w2.x; acc[1][1] += h4.y * w2.y;
                    acc[2][0] += h4.z * w2.x; acc[2][1] += h4.z * w2.y;
                    acc[3][0] += h4.w * w2.x; acc[3][1] += h4.w * w2.y;
                }
                __syncthreads();
            }
        }
#pragma unroll
        for (int j = 0; j < 2; j++)
#pragma unroll
            for (int i = 0; i < 4; i++) gsp[(b0 + i) * 33 + cc0 + j] = acc[i][j];
        __syncthreads();

        float* hout = ((s & 1) ? hA : hB) + dir * B_ * NC_;
#pragma unroll
        for (int r = 0; r < 2; r++) {
            int b = r ? eb1 : eb0;
            int jj = r ? ej1 : ej0;
            float gi = gsp[b * 33 + jj];
            float gf = gsp[b * 33 + 8 + jj];
            float gg = gsp[b * 33 + 16 + jj];
            float go = gsp[b * 33 + 24 + jj];
            float fi = 1.f / (1.f + expf(-gi));
            float ff = 1.f / (1.f + expf(-gf));
            float fo = 1.f / (1.f + expf(-go));
            float cn = ff * creg[r] + fi * tanhf(gg);
            float hv = fo * tanhf(cn);
            creg[r] = cn;
            hout[b * NC_ + j0 + jj] = hv;
            hcat[((size_t)b * T_ + t) * NH_ + dir * NC_ + j0 + jj] = hv;
        }
        __syncthreads();

        if (tid == 0) {
            unsigned target = base + (unsigned)s + 1u;
            __threadfence();
            unsigned old = atomicAdd(&g_bar_count, 1u);
            if (old == 127u) {
                atomicExch(&g_bar_count, 0u);
                __threadfence();
                atomicExch(&g_bar_sense, target);
            } else {
                while ((int)(*(volatile unsigned*)&g_bar_sense - target) < 0) { }
                __threadfence();
            }
        }
        __syncthreads();
    }
}

// attention pool + classifier, one CTA per batch
__global__ __launch_bounds__(256) void attn_out(
    const float* __restrict__ H, const int* __restrict__ lens,
    const float* __restrict__ w_u, const float* __restrict__ b_u,
    const float* __restrict__ Wc, const float* __restrict__ bc,
    float* __restrict__ out)
{
    __shared__ float sc[T_];
    __shared__ float pooled[NH_];
    __shared__ float red[8];
    int b = blockIdx.x;
    int tid = threadIdx.x, lane = tid & 31, w = tid >> 5;
    int len = lens[b];
    const float* Hb = H + (size_t)b * T_ * NH_;

    for (int t = w; t < T_; t += 8) {
        const float* hp = Hb + (size_t)t * NH_;
        float s = 0.f;
        for (int d = lane; d < NH_; d += 32) s += hp[d] * w_u[d];
        s = warpSum(s);
        if (lane == 0) sc[t] = s + b_u[0];
    }
    __syncthreads();

    float m = -3.0e38f;
    for (int t = tid; t < len; t += 256) m = fmaxf(m, sc[t]);
    m = blockMax(m, red);

    float ps = 0.f;
    for (int t = tid; t < T_; t += 256) {
        float e = (t < len) ? expf(sc[t] - m) : 0.f;
        sc[t] = e; ps += e;
    }
    float S = blockSum(ps, red);
    float inv = 1.f / S;

    for (int d = tid; d < NH_; d += 256) {
        float a = 0.f;
        for (int t = 0; t < len; ++t) a += sc[t] * Hb[(size_t)t * NH_ + d];
        pooled[d] = a * inv;
    }
    __syncthreads();

    {
        const float* wc = Wc + (size_t)w * NH_;
        float s = 0.f;
        for (int d = lane; d < NH_; d += 32) s += pooled[d] * wc[d];
        s = warpSum(s);
        if (lane == 0) out[b * NOUT_ + w] = s + bc[w];
    }
}

extern "C" void kernel_launch(void* const* d_in, const int* in_sizes, int n_in,
                              void* d_out, int out_size)
{
    const float* x    = (const float*)d_in[0];
    const int*   lens = (const int*)d_in[1];
    const float* W1   = (const float*)d_in[2];
    const float* b1   = (const float*)d_in[3];
    const float* g1   = (const float*)d_in[4];
    const float* be1  = (const float*)d_in[5];
    const float* W2   = (const float*)d_in[6];
    const float* b2   = (const float*)d_in[7];
    const float* g2   = (const float*)d_in[8];
    const float* be2  = (const float*)d_in[9];
    const float* wih  = (const float*)d_in[10];
    const float* whh  = (const float*)d_in[11];
    const float* bih  = (const float*)d_in[12];
    const float* bhh  = (const float*)d_in[13];
    const float* w_u  = (const float*)d_in[14];
    const float* b_u  = (const float*)d_in[15];
    const float* Wc   = (const float*)d_in[16];
    const float* bc   = (const float*)d_in[17];
    float* out = (float*)d_out;
    (void)in_sizes; (void)n_in; (void)out_size;

    float *bufA, *bufB, *bufC, *bufD, *hA, *hB;
    cudaGetSymbolAddress((void**)&bufA, g_bufA);
    cudaGetSymbolAddress((void**)&bufB, g_bufB);
    cudaGetSymbolAddress((void**)&bufC, g_bufC);
    cudaGetSymbolAddress((void**)&bufD, g_bufD);
    cudaGetSymbolAddress((void**)&hA, g_hA);
    cudaGetSymbolAddress((void**)&hB, g_hB);

    cudaFuncSetAttribute(lstm_layer, cudaFuncAttributeMaxDynamicSharedMemorySize,
                         LSTM_SMEM);

    dim3 blk(256);
    dim3 gMLP(NH_ / 128, M_ / 128);
    dim3 gXP(H4_ / 128, M_ / 128);

    gemm_tf32<<<gMLP, blk>>>(x, W1, bufD, b1, nullptr, M_, NH_, FD_);
    ln_lrelu<<<M_, blk>>>(bufD, g1, be1, nullptr);
    gemm_tf32<<<gMLP, blk>>>(bufD, W2, bufC, b2, nullptr, M_, NH_, NH_);
    ln_lrelu<<<M_, blk>>>(bufC, g2, be2, lens);

    for (int layer = 0; layer < 2; ++layer) {
        const float* inbuf = (layer == 0) ? bufC : bufD;
        float* hcat = (layer == 0) ? bufD : bufC;
        size_t wo = (size_t)layer * 2 * H4_ * NH_;
        size_t ho = (size_t)layer * 2 * H4_ * NC_;
        size_t bo = (size_t)layer * 2 * H4_;

        gemm_tf32<<<gXP, blk>>>(inbuf, wih + wo, bufA,
                                bih + bo, bhh + bo, M_, H4_, NH_);
        gemm_tf32<<<gXP, blk>>>(inbuf, wih + wo + (size_t)H4_ * NH_, bufB,
                                bih + bo + H4_, bhh + bo + H4_, M_, H4_, NH_);

        lstm_layer<<<128, 128, LSTM_SMEM>>>(bufA, bufB, whh + ho, hA, hB, hcat);
    }

    attn_out<<<B_, blk>>>(bufC, lens, w_u, b_u, Wc, bc, out);
}

// round 8
// speedup vs baseline: 1.8281x; 1.4278x over previous
#include <cuda_runtime.h>
#include <math.h>
#include <stdint.h>

#define B_    32
#define T_    512
#define FD_   256
#define NH_   1024
#define NC_   512
#define H4_   2048
#define NOUT_ 8
#define M_    (B_ * T_)

__device__ float g_bufA[(size_t)M_ * H4_];
__device__ float g_bufB[(size_t)M_ * H4_];
__device__ float g_bufC[(size_t)M_ * NH_];
__device__ float g_bufD[(size_t)M_ * NH_];
__device__ uint32_t g_hA[2 * B_ * NC_];
__device__ uint32_t g_hB[2 * B_ * NC_];
__device__ unsigned g_bar_count;
__device__ unsigned g_bar_sense;

__device__ __forceinline__ float warpSum(float v) {
#pragma unroll
    for (int o = 16; o > 0; o >>= 1) v += __shfl_xor_sync(0xffffffffu, v, o);
    return v;
}
__device__ __forceinline__ float warpMax(float v) {
#pragma unroll
    for (int o = 16; o > 0; o >>= 1) v = fmaxf(v, __shfl_xor_sync(0xffffffffu, v, o));
    return v;
}
__device__ __forceinline__ float blockSum(float v, float* sh) {
    int lane = threadIdx.x & 31, w = threadIdx.x >> 5;
    v = warpSum(v);
    if (lane == 0) sh[w] = v;
    __syncthreads();
    if (w == 0) {
        float r = (lane < 8) ? sh[lane] : 0.f;
        r = warpSum(r);
        if (lane == 0) sh[0] = r;
    }
    __syncthreads();
    float r = sh[0];
    __syncthreads();
    return r;
}
__device__ __forceinline__ float blockMax(float v, float* sh) {
    int lane = threadIdx.x & 31, w = threadIdx.x >> 5;
    v = warpMax(v);
    if (lane == 0) sh[w] = v;
    __syncthreads();
    if (w == 0) {
        float r = (lane < 8) ? sh[lane] : -3.0e38f;
        r = warpMax(r);
        if (lane == 0) sh[0] = r;
    }
    __syncthreads();
    float r = sh[0];
    __syncthreads();
    return r;
}

__device__ __forceinline__ uint32_t f2tf32(float f) {
    uint32_t r;
    asm("cvt.rna.tf32.f32 %0, %1;" : "=r"(r) : "f"(f));
    return r;
}

__device__ __forceinline__ void mma_tf32(float* c, const uint32_t* a, const uint32_t* b) {
    asm volatile(
        "mma.sync.aligned.m16n8k8.row.col.f32.tf32.tf32.f32 "
        "{%0,%1,%2,%3}, {%4,%5,%6,%7}, {%8,%9}, {%0,%1,%2,%3};"
        : "+f"(c[0]), "+f"(c[1]), "+f"(c[2]), "+f"(c[3])
        : "r"(a[0]), "r"(a[1]), "r"(a[2]), "r"(a[3]), "r"(b[0]), "r"(b[1]));
}

// ---- tf32 tensor-core GEMM: C[M,N] = A[M,K] @ W[N,K]^T + bias1 (+bias2) ----
__global__ __launch_bounds__(256) void gemm_tf32(
    const float* __restrict__ A, const float* __restrict__ W,
    float* __restrict__ C, const float* __restrict__ bias1,
    const float* __restrict__ bias2, int M, int N, int K)
{
    __shared__ uint32_t As[128][36];
    __shared__ uint32_t Bs[128][36];
    int tid = threadIdx.x;
    int lane = tid & 31, warp = tid >> 5;
    int wm = warp >> 2, wn = warp & 3;
    int lr = lane >> 2, lc = lane & 3;
    int bm = blockIdx.y * 128, bn = blockIdx.x * 128;

    float acc[4][4][4];
#pragma unroll
    for (int mt = 0; mt < 4; mt++)
#pragma unroll
        for (int nt = 0; nt < 4; nt++)
#pragma unroll
            for (int q = 0; q < 4; q++) acc[mt][nt][q] = 0.f;

    for (int k0 = 0; k0 < K; k0 += 32) {
#pragma unroll
        for (int i = 0; i < 4; i++) {
            int f = tid + (i << 8);
            int row = f >> 3, c4 = (f & 7) << 2;
            float4 a4 = *(const float4*)(A + (size_t)(bm + row) * K + k0 + c4);
            float4 b4 = *(const float4*)(W + (size_t)(bn + row) * K + k0 + c4);
            uint4 ta, tb;
            ta.x = f2tf32(a4.x); ta.y = f2tf32(a4.y);
            ta.z = f2tf32(a4.z); ta.w = f2tf32(a4.w);
            tb.x = f2tf32(b4.x); tb.y = f2tf32(b4.y);
            tb.z = f2tf32(b4.z); tb.w = f2tf32(b4.w);
            *(uint4*)&As[row][c4] = ta;
            *(uint4*)&Bs[row][c4] = tb;
        }
        __syncthreads();
#pragma unroll
        for (int ks = 0; ks < 4; ks++) {
            int kc = ks << 3;
            uint32_t af[4][4], bf[4][2];
#pragma unroll
            for (int mt = 0; mt < 4; mt++) {
                int rb = wm * 64 + mt * 16;
                af[mt][0] = As[rb + lr][kc + lc];
                af[mt][1] = As[rb + lr + 8][kc + lc];
                af[mt][2] = As[rb + lr][kc + lc + 4];
                af[mt][3] = As[rb + lr + 8][kc + lc + 4];
            }
#pragma unroll
            for (int nt = 0; nt < 4; nt++) {
                int nb = wn * 32 + nt * 8;
                bf[nt][0] = Bs[nb + lr][kc + lc];
                bf[nt][1] = Bs[nb + lr][kc + lc + 4];
            }
#pragma unroll
            for (int mt = 0; mt < 4; mt++)
#pragma unroll
                for (int nt = 0; nt < 4; nt++)
                    mma_tf32(acc[mt][nt], af[mt], bf[nt]);
        }
        __syncthreads();
    }

#pragma unroll
    for (int nt = 0; nt < 4; nt++) {
        int col = bn + wn * 32 + nt * 8 + (lc << 1);
        float b0 = bias1 ? bias1[col] : 0.f;
        float b1 = bias1 ? bias1[col + 1] : 0.f;
        if (bias2) { b0 += bias2[col]; b1 += bias2[col + 1]; }
#pragma unroll
        for (int mt = 0; mt < 4; mt++) {
            int row = bm + wm * 64 + mt * 16 + lr;
            float2 v0 = make_float2(acc[mt][nt][0] + b0, acc[mt][nt][1] + b1);
            float2 v1 = make_float2(acc[mt][nt][2] + b0, acc[mt][nt][3] + b1);
            *(float2*)(C + (size_t)row * N + col) = v0;
            *(float2*)(C + (size_t)(row + 8) * N + col) = v1;
        }
    }
}

// LayerNorm + LeakyReLU (+ pad-mask zero) in place
__global__ __launch_bounds__(256) void ln_lrelu(
    float* __restrict__ X, const float* __restrict__ g,
    const float* __restrict__ be, const int* __restrict__ lens)
{
    __shared__ float sh[8];
    int row = blockIdx.x;
    float* x = X + (size_t)row * NH_;
    int tid = threadIdx.x;
    float v[4], s = 0.f, ss = 0.f;
#pragma unroll
    for (int i = 0; i < 4; i++) {
        float t = x[tid + (i << 8)];
        v[i] = t; s += t; ss += t * t;
    }
    float S = blockSum(s, sh);
    float SS = blockSum(ss, sh);
    float mean = S * (1.f / NH_);
    float inv = rsqrtf(SS * (1.f / NH_) - mean * mean + 1e-5f);
    bool z = false;
    if (lens) z = ((row & (T_ - 1)) >= lens[row >> 9]);
#pragma unroll
    for (int i = 0; i < 4; i++) {
        int c = tid + (i << 8);
        float y = (v[i] - mean) * inv * g[c] + be[c];
        y = (y >= 0.f) ? y : 0.01f * y;
        x[c] = z ? 0.f : y;
    }
}

// ---- persistent bidirectional LSTM layer, tensor-core recurrence ----
// 128 CTAs = 2 dirs x 64 chunks (8 hidden cols each), 128 threads (4 warps = 4 gates).
// h stored in global as tf32 bits, k-permuted so fragment pairs (k, k+4) are adjacent.
#define LS_STRIDE 520
#define LS_H_OFF  (32 * LS_STRIDE)
#define LS_G_OFF  (64 * LS_STRIDE)
#define LSTM_SMEM ((64 * LS_STRIDE + 4 * 32 * 8) * 4)

__global__ __launch_bounds__(128) void lstm_layer(
    const float* __restrict__ xpf, const float* __restrict__ xpb,
    const float* __restrict__ whh,
    uint32_t* __restrict__ hA, uint32_t* __restrict__ hB,
    float* __restrict__ hcat)
{
    extern __shared__ float sm[];
    uint32_t* Wsm = (uint32_t*)sm;                  // [32 n][520] tf32, k-permuted
    uint32_t* hsp = (uint32_t*)(sm + LS_H_OFF);     // [32 b][520] tf32, k-permuted
    float*    gsm = sm + LS_G_OFF;                  // [4 gate][32 b][8 jj]
    __shared__ unsigned sh_base;

    int dir = blockIdx.x >> 6;
    int j0 = (blockIdx.x & 63) << 3;
    const float* xp = dir ? xpb : xpf;
    const float* W = whh + (size_t)dir * H4_ * NC_;
    int tid = threadIdx.x;
    int w = tid >> 5, lane = tid & 31;
    int lr = lane >> 2, lc = lane & 3;

    // cache + convert + permute whh slice (32 gate-cols x 512 k)
    for (int f = tid; f < 32 * 512; f += 128) {
        int n = f >> 9, k = f & 511;
        int g_ = n >> 3, jj = n & 7;
        float wv = W[(size_t)(g_ * NC_ + j0 + jj) * NC_ + k];
        int kp = (k & ~7) | ((k & 3) << 1) | ((k >> 2) & 1);
        Wsm[n * LS_STRIDE + kp] = f2tf32(wv);
    }
    if (tid == 0) sh_base = *(volatile unsigned*)&g_bar_sense;
    __syncthreads();
    unsigned base = sh_base;

    float creg[2] = {0.f, 0.f};

    const uint32_t* hr0 = hsp + lr * LS_STRIDE + 2 * lc;
    const uint32_t* wb  = Wsm + (w * 8 + lr) * LS_STRIDE + 2 * lc;
    size_t xcol = (size_t)w * NC_ + j0 + 2 * lc;

    for (int s = 0; s < T_; ++s) {
        int t = dir ? (T_ - 1 - s) : s;
        // prefetch xp early (independent of h)
        float2 x0, x1, x2, x3;
        {
            size_t tb = (size_t)t * H4_ + xcol;
            x0 = *(const float2*)(xp + ((size_t)(lr)      * T_) * H4_ + tb);
            x1 = *(const float2*)(xp + ((size_t)(lr + 8)  * T_) * H4_ + tb);
            x2 = *(const float2*)(xp + ((size_t)(lr + 16) * T_) * H4_ + tb);
            x3 = *(const float2*)(xp + ((size_t)(lr + 24) * T_) * H4_ + tb);
        }
        float a0a[4] = {0,0,0,0}, a0b[4] = {0,0,0,0};
        float a1a[4] = {0,0,0,0}, a1b[4] = {0,0,0,0};
        if (s > 0) {
            const uint32_t* hin = ((s & 1) ? hB : hA) + dir * B_ * NC_;
            // stage full h tile (already tf32 + permuted) 32x512
#pragma unroll
            for (int i = 0; i < 32; i++) {
                int row = i;
                uint4 v = *(const uint4*)(hin + row * NC_ + tid * 4);
                *(uint4*)(hsp + row * LS_STRIDE + tid * 4) = v;
            }
            __syncthreads();
#pragma unroll 4
            for (int kc = 0; kc < 512; kc += 16) {
                uint2 p0 = *(const uint2*)(hr0 + kc);
                uint2 p1 = *(const uint2*)(hr0 + 8 * LS_STRIDE + kc);
                uint2 p2 = *(const uint2*)(hr0 + 16 * LS_STRIDE + kc);
                uint2 p3 = *(const uint2*)(hr0 + 24 * LS_STRIDE + kc);
                uint2 bv = *(const uint2*)(wb + kc);
                uint32_t A0[4] = {p0.x, p1.x, p0.y, p1.y};
                uint32_t A1[4] = {p2.x, p3.x, p2.y, p3.y};
                uint32_t Bf[2] = {bv.x, bv.y};
                mma_tf32(a0a, A0, Bf);
                mma_tf32(a1a, A1, Bf);
                uint2 q0 = *(const uint2*)(hr0 + kc + 8);
                uint2 q1 = *(const uint2*)(hr0 + 8 * LS_STRIDE + kc + 8);
                uint2 q2 = *(const uint2*)(hr0 + 16 * LS_STRIDE + kc + 8);
                uint2 q3 = *(const uint2*)(hr0 + 24 * LS_STRIDE + kc + 8);
                uint2 bw = *(const uint2*)(wb + kc + 8);
                uint32_t A0b[4] = {q0.x, q1.x, q0.y, q1.y};
                uint32_t A1b[4] = {q2.x, q3.x, q2.y, q3.y};
                uint32_t Bg[2] = {bw.x, bw.y};
                mma_tf32(a0b, A0b, Bg);
                mma_tf32(a1b, A1b, Bg);
            }
        }
        // merge chains + add xp, write gates to smem
        {
            float* gw = gsm + w * 256;
            *(float2*)(gw + lr * 8 + 2 * lc) =
                make_float2(a0a[0] + a0b[0] + x0.x, a0a[1] + a0b[1] + x0.y);
            *(float2*)(gw + (lr + 8) * 8 + 2 * lc) =
                make_float2(a0a[2] + a0b[2] + x1.x, a0a[3] + a0b[3] + x1.y);
            *(float2*)(gw + (lr + 16) * 8 + 2 * lc) =
                make_float2(a1a[0] + a1b[0] + x2.x, a1a[1] + a1b[1] + x2.y);
            *(float2*)(gw + (lr + 24) * 8 + 2 * lc) =
                make_float2(a1a[2] + a1b[2] + x3.x, a1a[3] + a1b[3] + x3.y);
        }
        __syncthreads();

        uint32_t* hout = ((s & 1) ? hA : hB) + dir * B_ * NC_;
#pragma unroll
        for (int r = 0; r < 2; r++) {
            int e = tid + (r << 7);
            int b = e >> 3, jj = e & 7;
            float gi = gsm[b * 8 + jj];
            float gf = gsm[256 + b * 8 + jj];
            float gg = gsm[512 + b * 8 + jj];
            float go = gsm[768 + b * 8 + jj];
            float fi = 1.f / (1.f + expf(-gi));
            float ff = 1.f / (1.f + expf(-gf));
            float fo = 1.f / (1.f + expf(-go));
            float cn = ff * creg[r] + fi * tanhf(gg);
            float hv = fo * tanhf(cn);
            creg[r] = cn;
            int kp = j0 + (((jj & 3) << 1) | (jj >> 2));
            hout[b * NC_ + kp] = f2tf32(hv);
            hcat[((size_t)b * T_ + t) * NH_ + dir * NC_ + j0 + jj] = hv;
        }
        __syncthreads();

        // grid-wide barrier (sense-reversing, wrap-safe)
        if (tid == 0) {
            unsigned target = base + (unsigned)s + 1u;
            __threadfence();
            unsigned old = atomicAdd(&g_bar_count, 1u);
            if (old == 127u) {
                atomicExch(&g_bar_count, 0u);
                __threadfence();
                atomicExch(&g_bar_sense, target);
            } else {
                while ((int)(*(volatile unsigned*)&g_bar_sense - target) < 0) { }
                __threadfence();
            }
        }
        __syncthreads();
    }
}

// attention pool + classifier, one CTA per batch
__global__ __launch_bounds__(256) void attn_out(
    const float* __restrict__ H, const int* __restrict__ lens,
    const float* __restrict__ w_u, const float* __restrict__ b_u,
    const float* __restrict__ Wc, const float* __restrict__ bc,
    float* __restrict__ out)
{
    __shared__ float sc[T_];
    __shared__ float pooled[NH_];
    __shared__ float red[8];
    int b = blockIdx.x;
    int tid = threadIdx.x, lane = tid & 31, w = tid >> 5;
    int len = lens[b];
    const float* Hb = H + (size_t)b * T_ * NH_;

    for (int t = w; t < T_; t += 8) {
        const float* hp = Hb + (size_t)t * NH_;
        float s = 0.f;
        for (int d = lane; d < NH_; d += 32) s += hp[d] * w_u[d];
        s = warpSum(s);
        if (lane == 0) sc[t] = s + b_u[0];
    }
    __syncthreads();

    float m = -3.0e38f;
    for (int t = tid; t < len; t += 256) m = fmaxf(m, sc[t]);
    m = blockMax(m, red);

    float ps = 0.f;
    for (int t = tid; t < T_; t += 256) {
        float e = (t < len) ? expf(sc[t] - m) : 0.f;
        sc[t] = e; ps += e;
    }
    float S = blockSum(ps, red);
    float inv = 1.f / S;

    // coalesced pooled accumulation (loop over t outer, d strided by tid)
    {
        float a0 = 0.f, a1 = 0.f, a2 = 0.f, a3 = 0.f;
        for (int t = 0; t < len; ++t) {
            float al = sc[t];
            const float* hp = Hb + (size_t)t * NH_ + tid;
            a0 += al * hp[0];
            a1 += al * hp[256];
            a2 += al * hp[512];
            a3 += al * hp[768];
        }
        pooled[tid]       = a0 * inv;
        pooled[tid + 256] = a1 * inv;
        pooled[tid + 512] = a2 * inv;
        pooled[tid + 768] = a3 * inv;
    }
    __syncthreads();

    {
        const float* wc = Wc + (size_t)w * NH_;
        float s = 0.f;
        for (int d = lane; d < NH_; d += 32) s += pooled[d] * wc[d];
        s = warpSum(s);
        if (lane == 0) out[b * NOUT_ + w] = s + bc[w];
    }
}

extern "C" void kernel_launch(void* const* d_in, const int* in_sizes, int n_in,
                              void* d_out, int out_size)
{
    const float* x    = (const float*)d_in[0];
    const int*   lens = (const int*)d_in[1];
    const float* W1   = (const float*)d_in[2];
    const float* b1   = (const float*)d_in[3];
    const float* g1   = (const float*)d_in[4];
    const float* be1  = (const float*)d_in[5];
    const float* W2   = (const float*)d_in[6];
    const float* b2   = (const float*)d_in[7];
    const float* g2   = (const float*)d_in[8];
    const float* be2  = (const float*)d_in[9];
    const float* wih  = (const float*)d_in[10];
    const float* whh  = (const float*)d_in[11];
    const float* bih  = (const float*)d_in[12];
    const float* bhh  = (const float*)d_in[13];
    const float* w_u  = (const float*)d_in[14];
    const float* b_u  = (const float*)d_in[15];
    const float* Wc   = (const float*)d_in[16];
    const float* bc   = (const float*)d_in[17];
    float* out = (float*)d_out;
    (void)in_sizes; (void)n_in; (void)out_size;

    float *bufA, *bufB, *bufC, *bufD;
    uint32_t *hA, *hB;
    cudaGetSymbolAddress((void**)&bufA, g_bufA);
    cudaGetSymbolAddress((void**)&bufB, g_bufB);
    cudaGetSymbolAddress((void**)&bufC, g_bufC);
    cudaGetSymbolAddress((void**)&bufD, g_bufD);
    cudaGetSymbolAddress((void**)&hA, g_hA);
    cudaGetSymbolAddress((void**)&hB, g_hB);

    cudaFuncSetAttribute(lstm_layer, cudaFuncAttributeMaxDynamicSharedMemorySize,
                         LSTM_SMEM);

    dim3 blk(256);
    dim3 gMLP(NH_ / 128, M_ / 128);
    dim3 gXP(H4_ / 128, M_ / 128);

    gemm_tf32<<<gMLP, blk>>>(x, W1, bufD, b1, nullptr, M_, NH_, FD_);
    ln_lrelu<<<M_, blk>>>(bufD, g1, be1, nullptr);
    gemm_tf32<<<gMLP, blk>>>(bufD, W2, bufC, b2, nullptr, M_, NH_, NH_);
    ln_lrelu<<<M_, blk>>>(bufC, g2, be2, lens);

    for (int layer = 0; layer < 2; ++layer) {
        const float* inbuf = (layer == 0) ? bufC : bufD;
        float* hcat = (layer == 0) ? bufD : bufC;
        size_t wo = (size_t)layer * 2 * H4_ * NH_;
        size_t ho = (size_t)layer * 2 * H4_ * NC_;
        size_t bo = (size_t)layer * 2 * H4_;

        gemm_tf32<<<gXP, blk>>>(inbuf, wih + wo, bufA,
                                bih + bo, bhh + bo, M_, H4_, NH_);
        gemm_tf32<<<gXP, blk>>>(inbuf, wih + wo + (size_t)H4_ * NH_, bufB,
                                bih + bo + H4_, bhh + bo + H4_, M_, H4_, NH_);

        lstm_layer<<<128, 128, LSTM_SMEM>>>(bufA, bufB, whh + ho, hA, hB, hcat);
    }

    attn_out<<<B_, blk>>>(bufC, lens, w_u, b_u, Wc, bc, out);
}